// round 9
// baseline (speedup 1.0000x reference)
#include <cuda_runtime.h>
#include <cuda_fp16.h>
#include <math.h>
#include <stdint.h>

// ---------------------------------------------------------------------------
#define B_ 8
#define S_ 2048
#define D_ 1024
#define F_ 4096
#define E_ 8

// ---------------------------------------------------------------------------
// Scratch (__device__ globals). Everything single fp16, K-major.
// ---------------------------------------------------------------------------
__device__ __half g_xf[(size_t)B_ * S_ * D_];
__device__ __half g_w1f[(size_t)E_ * D_ * F_];
__device__ __half g_w3f[(size_t)E_ * D_ * F_];
__device__ __half g_w2f[(size_t)E_ * F_ * D_];
__device__ __half g_hf[(size_t)B_ * S_ * F_];

// ---------------------------------------------------------------------------
// PTX helpers (base-target-safe)
// ---------------------------------------------------------------------------
__device__ __forceinline__ uint32_t smem_to_u32(const void* p) {
    uint32_t a;
    asm("{ .reg .u64 t; cvta.to.shared.u64 t, %1; cvt.u32.u64 %0, t; }" : "=r"(a) : "l"(p));
    return a;
}
#define CP_ASYNC16(saddr, gptr) \
    asm volatile("cp.async.cg.shared.global [%0], [%1], 16;" :: "r"(saddr), "l"(gptr))
#define CP_COMMIT()  asm volatile("cp.async.commit_group;" ::: "memory")
#define CP_WAIT1()   asm volatile("cp.async.wait_group 1;" ::: "memory")

__device__ __forceinline__ void ldsm_x4(uint32_t& r0, uint32_t& r1, uint32_t& r2,
                                        uint32_t& r3, uint32_t addr) {
    asm volatile("ldmatrix.sync.aligned.m8n8.x4.shared.b16 {%0,%1,%2,%3}, [%4];"
                 : "=r"(r0), "=r"(r1), "=r"(r2), "=r"(r3) : "r"(addr));
}
__device__ __forceinline__ void ldsm_x4_t(uint32_t& r0, uint32_t& r1, uint32_t& r2,
                                          uint32_t& r3, uint32_t addr) {
    asm volatile("ldmatrix.sync.aligned.m8n8.x4.trans.shared.b16 {%0,%1,%2,%3}, [%4];"
                 : "=r"(r0), "=r"(r1), "=r"(r2), "=r"(r3) : "r"(addr));
}
__device__ __forceinline__ void mma_16816(float* d, const uint32_t* a, const uint32_t* b) {
    asm volatile(
        "mma.sync.aligned.m16n8k16.row.col.f32.f16.f16.f32 "
        "{%0,%1,%2,%3}, {%4,%5,%6,%7}, {%8,%9}, {%0,%1,%2,%3};"
        : "+f"(d[0]), "+f"(d[1]), "+f"(d[2]), "+f"(d[3])
        : "r"(a[0]), "r"(a[1]), "r"(a[2]), "r"(a[3]), "r"(b[0]), "r"(b[1]));
}

// ---------------------------------------------------------------------------
// Prep kernels
// ---------------------------------------------------------------------------
__global__ __launch_bounds__(256)
void zero_kernel(float4* __restrict__ out, long n4)
{
    long i = (long)blockIdx.x * blockDim.x + threadIdx.x;
    if (i < n4) out[i] = make_float4(0.f, 0.f, 0.f, 0.f);
}

__global__ __launch_bounds__(256)
void convert_x_kernel(const float* __restrict__ src, __half* __restrict__ dst, long n4)
{
    long i = (long)blockIdx.x * blockDim.x + threadIdx.x;
    if (i >= n4) return;
    float4 v = ((const float4*)src)[i];
    union { uint2 u; __half h[4]; } p;
    p.h[0] = __float2half_rn(v.x);
    p.h[1] = __float2half_rn(v.y);
    p.h[2] = __float2half_rn(v.z);
    p.h[3] = __float2half_rn(v.w);
    ((uint2*)dst)[i] = p.u;
}

// weight conversion, expert-gated.  grid: (blocksPerExpert, 3, E_)
__global__ __launch_bounds__(256)
void convert_w_kernel(const float* __restrict__ w1,
                      const float* __restrict__ w3,
                      const float* __restrict__ w2,
                      __half* __restrict__ w1f,
                      __half* __restrict__ w3f,
                      __half* __restrict__ w2f,
                      const int* __restrict__ langs)
{
    const int e = blockIdx.z;
    int used = 0;
#pragma unroll
    for (int b = 0; b < B_; b++)
        if (langs[b] - 4 == e) used = 1;
    if (!used) return;
    const long per = (long)D_ * F_ / 4;
    long i = e * per + (long)blockIdx.x * blockDim.x + threadIdx.x;
    const float* src = (blockIdx.y == 0) ? w1 : (blockIdx.y == 1) ? w3 : w2;
    __half* dst = (blockIdx.y == 0) ? w1f : (blockIdx.y == 1) ? w3f : w2f;
    float4 v = ((const float4*)src)[i];
    union { uint2 u; __half h[4]; } p;
    p.h[0] = __float2half_rn(v.x);
    p.h[1] = __float2half_rn(v.y);
    p.h[2] = __float2half_rn(v.z);
    p.h[3] = __float2half_rn(v.w);
    ((uint2*)dst)[i] = p.u;
}

// ---------------------------------------------------------------------------
// Layout constants (BK=64, swizzled, no padding)
// ---------------------------------------------------------------------------
#define BK 64
#define A_ARR 16384                    // 128 rows x 128B
#define FB_ARR 8192                    // 64 k-rows x 128B
#define F_STAGE (A_ARR + 2*FB_ARR)     // 32768
#define F_SMEM  (3 * F_STAGE)          // 98304
#define GB_ARR 16384                   // 64 k-rows x 256B
#define G_STAGE (A_ARR + GB_ARR)       // 32768
#define G_SMEM  (3 * G_STAGE)          // 98304

// A rows 128B wide, 8 chunks of 16B:  c' = c ^ (row&7)
__device__ __forceinline__ uint32_t a_off(int row, int c) {
    return (uint32_t)(row * 128 + ((c ^ (row & 7)) << 4));
}
// B (gemm12) rows 128B wide, 8 chunks
__device__ __forceinline__ uint32_t fb_off(int row, int c) {
    return (uint32_t)(row * 128 + ((c ^ (row & 7)) << 4));
}
// B (gemm3) rows 256B wide, 16 chunks
__device__ __forceinline__ uint32_t gb_off(int row, int c) {
    return (uint32_t)(row * 256 + ((c ^ (row & 7)) << 4));
}

// ===========================================================================
// FUSED: a = x@W1, b = x@W3; h = gelu(a)*b -> fp16
// CTA 128m x 64n x 2 outputs, 8 warps: out_sel=wid>>2; wm=(wid&3)>>1, wn=wid&1.
// BK=64, 3-stage, one __syncthreads per chunk, 2 CTAs/SM.
// ===========================================================================
__device__ __forceinline__ void f_load_stage(
    uint32_t st,
    const __half* __restrict__ Af,
    const __half* __restrict__ B1, const __half* __restrict__ B3,
    long aRow0, long wBase, int n0, int kb, int tid)
{
#pragma unroll
    for (int j = 0; j < 4; j++) {        // A: 128 rows x 8 chunks
        int i = tid + j * 256;
        int row = i >> 3, c16 = i & 7;
        CP_ASYNC16(st + a_off(row, c16), Af + (aRow0 + row) * (long)D_ + kb + c16 * 8);
    }
#pragma unroll
    for (int j = 0; j < 4; j++) {        // B: 2 arrays x 64 k-rows x 8 chunks
        int i = tid + j * 256;
        int arr = i >> 9, row = (i >> 3) & 63, c16 = i & 7;
        uint32_t s = st + A_ARR + arr * FB_ARR + fb_off(row, c16);
        const __half* g = (arr ? B3 : B1)
            + wBase + (long)(kb + row) * F_ + n0 + c16 * 8;
        CP_ASYNC16(s, g);
    }
}

__global__ __launch_bounds__(256, 2)
void fused_gemm12_kernel(const __half* __restrict__ Af,
                         const __half* __restrict__ B1,
                         const __half* __restrict__ B3,
                         const int* __restrict__ langs,
                         __half* __restrict__ outH)
{
    extern __shared__ char smem[];
    const uint32_t sbase = smem_to_u32(smem);

    const int tid = threadIdx.x;
    const int wid = tid >> 5;
    const int lane = tid & 31;
    const int out_sel = wid >> 2;          // 0: W1(a), 1: W3(b)
    const int w4 = wid & 3;
    const int wm = w4 >> 1;
    const int wn = w4 & 1;

    const int bz = blockIdx.z;
    const int m0 = blockIdx.y * 128;
    const int n0 = blockIdx.x * 64;

    const int lang = langs[bz];
    int e = lang - 4; if (e < 0) e = 0; if (e > 7) e = 7;

    const long aRow0 = (long)bz * S_ + m0;
    const long wBase = (long)e * D_ * F_;
    const int NC = D_ / BK;    // 16

    float acc[4][4][4];
#pragma unroll
    for (int i = 0; i < 4; i++)
#pragma unroll
        for (int j = 0; j < 4; j++)
#pragma unroll
            for (int q = 0; q < 4; q++) acc[i][j][q] = 0.0f;

    f_load_stage(sbase, Af, B1, B3, aRow0, wBase, n0, 0, tid);
    CP_COMMIT();
    f_load_stage(sbase + F_STAGE, Af, B1, B3, aRow0, wBase, n0, BK, tid);
    CP_COMMIT();

    const uint32_t stBoff = A_ARR + out_sel * FB_ARR;
    int sIdx = 0, sNext = 2;

    for (int c = 0; c < NC; ++c) {
        CP_WAIT1();
        __syncthreads();
        if (c + 2 < NC)
            f_load_stage(sbase + sNext * F_STAGE, Af, B1, B3,
                         aRow0, wBase, n0, (c + 2) * BK, tid);
        CP_COMMIT();

        const uint32_t st = sbase + sIdx * F_STAGE;
        const uint32_t stB = st + stBoff;
#pragma unroll
        for (int ks = 0; ks < 4; ks++) {
            uint32_t bf[4][2];
#pragma unroll
            for (int half = 0; half < 2; half++) {
                int brow = ks * 16 + (lane & 15);
                int bc = wn * 4 + half * 2 + (lane >> 4);
                uint32_t r0, r1, r2, r3;
                ldsm_x4_t(r0, r1, r2, r3, stB + fb_off(brow, bc));
                bf[half * 2][0] = r0; bf[half * 2][1] = r1;
                bf[half * 2 + 1][0] = r2; bf[half * 2 + 1][1] = r3;
            }
#pragma unroll
            for (int mt = 0; mt < 4; mt++) {
                int row = wm * 64 + mt * 16 + (lane & 15);
                uint32_t off = a_off(row, ks * 2 + (lane >> 4));
                uint32_t af[4];
                ldsm_x4(af[0], af[1], af[2], af[3], st + off);
#pragma unroll
                for (int nt = 0; nt < 4; nt++)
                    mma_16816(acc[mt][nt], af, bf[nt]);
            }
        }
        sIdx = (sIdx == 2) ? 0 : sIdx + 1;
        sNext = (sNext == 2) ? 0 : sNext + 1;
    }

    // --- epilogue: a-warps dump acc to smem; b-warps apply gelu(a)*b ---
    __syncthreads();
    float* ex = (float*)smem;              // 32 KB needed, 96 KB available
    if (out_sel == 0) {
#pragma unroll
        for (int mt = 0; mt < 4; mt++)
#pragma unroll
            for (int nt = 0; nt < 4; nt++)
#pragma unroll
                for (int q = 0; q < 4; q++) {
                    int i = (mt * 4 + nt) * 4 + q;
                    ex[w4 * 2048 + i * 32 + lane] = acc[mt][nt][q];
                }
    }
    __syncthreads();
    if (out_sel == 1) {
        const int qr = lane >> 2;
        const int qc = (lane & 3) * 2;
#pragma unroll
        for (int mt = 0; mt < 4; mt++) {
#pragma unroll
            for (int half = 0; half < 2; half++) {
                const int gm = m0 + wm * 64 + mt * 16 + qr + half * 8;
                const long rowBase = ((long)bz * S_ + gm) * (long)F_;
#pragma unroll
                for (int nt = 0; nt < 4; nt++) {
                    const int gn = n0 + wn * 32 + nt * 8 + qc;
                    const long idx = rowBase + gn;
                    float b0 = acc[mt][nt][half * 2 + 0];
                    float b1 = acc[mt][nt][half * 2 + 1];
                    int i0 = (mt * 4 + nt) * 4 + half * 2;
                    float a0 = ex[w4 * 2048 + i0 * 32 + lane];
                    float a1 = ex[w4 * 2048 + (i0 + 1) * 32 + lane];
                    float g0 = 0.5f * a0 * (1.0f + erff(a0 * 0.70710678118654752f));
                    float g1 = 0.5f * a1 * (1.0f + erff(a1 * 0.70710678118654752f));
                    union { uint32_t u; __half h[2]; } uh;
                    uh.h[0] = __float2half_rn(g0 * b0);
                    uh.h[1] = __float2half_rn(g1 * b1);
                    *(uint32_t*)(outH + idx) = uh.u;
                }
            }
        }
    }
}

// ===========================================================================
// GEMM3 (split-K=2): out += rw * (h[.., Khalf] @ W2[Khalf, ..]) via REDG
// CTA 128m x 128n, 8 warps 2m x 4n of 64x32.  BK=64.
// ===========================================================================
__device__ __forceinline__ void g_load_stage(
    uint32_t st,
    const __half* __restrict__ Af, const __half* __restrict__ Bf,
    long aRow0, long wBase, int n0, int kb, int tid)
{
#pragma unroll
    for (int j = 0; j < 4; j++) {
        int i = tid + j * 256;
        int row = i >> 3, c16 = i & 7;
        CP_ASYNC16(st + a_off(row, c16), Af + (aRow0 + row) * (long)F_ + kb + c16 * 8);
    }
#pragma unroll
    for (int j = 0; j < 4; j++) {
        int i = tid + j * 256;
        int row = (i >> 4) & 63, c16 = i & 15;
        uint32_t s = st + A_ARR + gb_off(row, c16);
        CP_ASYNC16(s, Bf + wBase + (long)(kb + row) * D_ + n0 + c16 * 8);
    }
}

__global__ __launch_bounds__(256, 2)
void gemm3_kernel(const __half* __restrict__ Af,
                  const __half* __restrict__ Bf,
                  const int* __restrict__ langs,
                  float* __restrict__ out)
{
    extern __shared__ char smem[];
    const uint32_t sbase = smem_to_u32(smem);

    const int tid = threadIdx.x;
    const int wid = tid >> 5;
    const int lane = tid & 31;
    const int wm = wid >> 2;
    const int wn = wid & 3;

    const int z = blockIdx.z;
    const int bz = z >> 1;
    const int kh = z & 1;
    const int m0 = blockIdx.y * 128;
    const int n0 = blockIdx.x * 128;

    const int lang = langs[bz];
    int e = lang - 4; if (e < 0) e = 0; if (e > 7) e = 7;
    const int cnt = (lang > 3) ? 1 : 0;
    const float rw = (cnt == 0) ? 1.0f : (1.0f / (float)cnt);

    const long aRow0 = (long)bz * S_ + m0;
    const long wBase = (long)e * F_ * D_;
    const int kBase = kh * (F_ / 2);
    const int NC = (F_ / 2) / BK;         // 32

    float acc[4][4][4];
#pragma unroll
    for (int i = 0; i < 4; i++)
#pragma unroll
        for (int j = 0; j < 4; j++)
#pragma unroll
            for (int q = 0; q < 4; q++) acc[i][j][q] = 0.0f;

    g_load_stage(sbase, Af, Bf, aRow0, wBase, n0, kBase, tid);
    CP_COMMIT();
    g_load_stage(sbase + G_STAGE, Af, Bf, aRow0, wBase, n0, kBase + BK, tid);
    CP_COMMIT();

    int sIdx = 0, sNext = 2;

    for (int c = 0; c < NC; ++c) {
        CP_WAIT1();
        __syncthreads();
        if (c + 2 < NC)
            g_load_stage(sbase + sNext * G_STAGE, Af, Bf,
                         aRow0, wBase, n0, kBase + (c + 2) * BK, tid);
        CP_COMMIT();

        const uint32_t st = sbase + sIdx * G_STAGE;
        const uint32_t stB = st + A_ARR;
#pragma unroll
        for (int ks = 0; ks < 4; ks++) {
            uint32_t bf[4][2];
#pragma unroll
            for (int half = 0; half < 2; half++) {
                int brow = ks * 16 + (lane & 15);
                int bc = wn * 4 + half * 2 + (lane >> 4);
                uint32_t r0, r1, r2, r3;
                ldsm_x4_t(r0, r1, r2, r3, stB + gb_off(brow, bc));
                bf[half * 2][0] = r0; bf[half * 2][1] = r1;
                bf[half * 2 + 1][0] = r2; bf[half * 2 + 1][1] = r3;
            }
#pragma unroll
            for (int mt = 0; mt < 4; mt++) {
                int row = wm * 64 + mt * 16 + (lane & 15);
                uint32_t off = a_off(row, ks * 2 + (lane >> 4));
                uint32_t af[4];
                ldsm_x4(af[0], af[1], af[2], af[3], st + off);
#pragma unroll
                for (int nt = 0; nt < 4; nt++)
                    mma_16816(acc[mt][nt], af, bf[nt]);
            }
        }
        sIdx = (sIdx == 2) ? 0 : sIdx + 1;
        sNext = (sNext == 2) ? 0 : sNext + 1;
    }

    // epilogue: REDG-accumulate rw-scaled partials into pre-zeroed out
    const int qr = lane >> 2;
    const int qc = (lane & 3) * 2;
#pragma unroll
    for (int mt = 0; mt < 4; mt++) {
#pragma unroll
        for (int half = 0; half < 2; half++) {
            const int gm = m0 + wm * 64 + mt * 16 + qr + half * 8;
            const long rowBase = ((long)bz * S_ + gm) * (long)D_;
#pragma unroll
            for (int nt = 0; nt < 4; nt++) {
                const int gn = n0 + wn * 32 + nt * 8 + qc;
                atomicAdd(out + rowBase + gn, acc[mt][nt][half * 2] * rw);
                atomicAdd(out + rowBase + gn + 1, acc[mt][nt][half * 2 + 1] * rw);
            }
        }
    }
}

// ---------------------------------------------------------------------------
// Launch
// ---------------------------------------------------------------------------
extern "C" void kernel_launch(void* const* d_in, const int* in_sizes, int n_in,
                              void* d_out, int out_size)
{
    const float* x     = (const float*)d_in[0];
    const float* w1    = (const float*)d_in[1];
    const float* w2    = (const float*)d_in[2];
    const float* w3    = (const float*)d_in[3];
    const int*   langs = (const int*)  d_in[4];
    float* out = (float*)d_out;

    __half *xf, *w1f, *w3f, *w2f, *hf;
    cudaGetSymbolAddress((void**)&xf,  g_xf);
    cudaGetSymbolAddress((void**)&w1f, g_w1f);
    cudaGetSymbolAddress((void**)&w3f, g_w3f);
    cudaGetSymbolAddress((void**)&w2f, g_w2f);
    cudaGetSymbolAddress((void**)&hf,  g_hf);

    cudaFuncSetAttribute(fused_gemm12_kernel,
                         cudaFuncAttributeMaxDynamicSharedMemorySize, F_SMEM);
    cudaFuncSetAttribute(gemm3_kernel,
                         cudaFuncAttributeMaxDynamicSharedMemorySize, G_SMEM);

    // 0) zero output (REDG accumulation target)
    {
        long n4 = (long)B_ * S_ * D_ / 4;
        zero_kernel<<<(unsigned)(n4 / 256), 256>>>((float4*)out, n4);
    }
    // 1) prep: fp16 conversions (weights expert-gated)
    {
        long nx = (long)B_ * S_ * D_ / 4;
        convert_x_kernel<<<(unsigned)(nx / 256), 256>>>(x, xf, nx);
        unsigned wb = (unsigned)(((long)D_ * F_ / 4) / 256);
        dim3 gw(wb, 3, E_);
        convert_w_kernel<<<gw, 256>>>(w1, w3, w2, w1f, w3f, w2f, langs);
    }
    // 2) fused GEMM1+GEMM2 + GLU -> h (fp16)
    {
        dim3 grid(F_ / 64, S_ / 128, B_);
        fused_gemm12_kernel<<<grid, 256, F_SMEM>>>(xf, w1f, w3f, langs, hf);
    }
    // 3) GEMM3 split-K=2, REDG into out
    {
        dim3 grid(D_ / 128, S_ / 128, B_ * 2);
        gemm3_kernel<<<grid, 256, G_SMEM>>>(hf, w2f, langs, out);
    }
}

// round 10
// speedup vs baseline: 1.4341x; 1.4341x over previous
#include <cuda_runtime.h>
#include <cuda_fp16.h>
#include <math.h>
#include <stdint.h>

// ---------------------------------------------------------------------------
#define B_ 8
#define S_ 2048
#define D_ 1024
#define F_ 4096
#define E_ 8

// ---------------------------------------------------------------------------
// Scratch (__device__ globals). Everything single fp16, K-major.
// ---------------------------------------------------------------------------
__device__ __half g_xf[(size_t)B_ * S_ * D_];
__device__ __half g_w1f[(size_t)E_ * D_ * F_];
__device__ __half g_w3f[(size_t)E_ * D_ * F_];
__device__ __half g_w2f[(size_t)E_ * F_ * D_];
__device__ __half g_hf[(size_t)B_ * S_ * F_];

// ---------------------------------------------------------------------------
// PTX helpers (base-target-safe)
// ---------------------------------------------------------------------------
__device__ __forceinline__ uint32_t smem_to_u32(const void* p) {
    uint32_t a;
    asm("{ .reg .u64 t; cvta.to.shared.u64 t, %1; cvt.u32.u64 %0, t; }" : "=r"(a) : "l"(p));
    return a;
}
#define CP_ASYNC16(saddr, gptr) \
    asm volatile("cp.async.cg.shared.global [%0], [%1], 16;" :: "r"(saddr), "l"(gptr))
#define CP_COMMIT()  asm volatile("cp.async.commit_group;" ::: "memory")
#define CP_WAIT1()   asm volatile("cp.async.wait_group 1;" ::: "memory")

__device__ __forceinline__ void ldsm_x4(uint32_t& r0, uint32_t& r1, uint32_t& r2,
                                        uint32_t& r3, uint32_t addr) {
    asm volatile("ldmatrix.sync.aligned.m8n8.x4.shared.b16 {%0,%1,%2,%3}, [%4];"
                 : "=r"(r0), "=r"(r1), "=r"(r2), "=r"(r3) : "r"(addr));
}
__device__ __forceinline__ void ldsm_x4_t(uint32_t& r0, uint32_t& r1, uint32_t& r2,
                                          uint32_t& r3, uint32_t addr) {
    asm volatile("ldmatrix.sync.aligned.m8n8.x4.trans.shared.b16 {%0,%1,%2,%3}, [%4];"
                 : "=r"(r0), "=r"(r1), "=r"(r2), "=r"(r3) : "r"(addr));
}
__device__ __forceinline__ void mma_16816(float* d, const uint32_t* a, const uint32_t* b) {
    asm volatile(
        "mma.sync.aligned.m16n8k16.row.col.f32.f16.f16.f32 "
        "{%0,%1,%2,%3}, {%4,%5,%6,%7}, {%8,%9}, {%0,%1,%2,%3};"
        : "+f"(d[0]), "+f"(d[1]), "+f"(d[2]), "+f"(d[3])
        : "r"(a[0]), "r"(a[1]), "r"(a[2]), "r"(a[3]), "r"(b[0]), "r"(b[1]));
}

// ---------------------------------------------------------------------------
// Prep kernels
// ---------------------------------------------------------------------------
__global__ __launch_bounds__(256)
void zero_kernel(float4* __restrict__ out, long n4)
{
    long i = (long)blockIdx.x * blockDim.x + threadIdx.x;
    if (i < n4) out[i] = make_float4(0.f, 0.f, 0.f, 0.f);
}

__global__ __launch_bounds__(256)
void convert_x_kernel(const float* __restrict__ src, __half* __restrict__ dst, long n4)
{
    long i = (long)blockIdx.x * blockDim.x + threadIdx.x;
    if (i >= n4) return;
    float4 v = ((const float4*)src)[i];
    union { uint2 u; __half h[4]; } p;
    p.h[0] = __float2half_rn(v.x);
    p.h[1] = __float2half_rn(v.y);
    p.h[2] = __float2half_rn(v.z);
    p.h[3] = __float2half_rn(v.w);
    ((uint2*)dst)[i] = p.u;
}

// weight conversion, expert-gated.  grid: (blocksPerExpert, 3, E_)
__global__ __launch_bounds__(256)
void convert_w_kernel(const float* __restrict__ w1,
                      const float* __restrict__ w3,
                      const float* __restrict__ w2,
                      __half* __restrict__ w1f,
                      __half* __restrict__ w3f,
                      __half* __restrict__ w2f,
                      const int* __restrict__ langs)
{
    const int e = blockIdx.z;
    int used = 0;
#pragma unroll
    for (int b = 0; b < B_; b++)
        if (langs[b] - 4 == e) used = 1;
    if (!used) return;
    const long per = (long)D_ * F_ / 4;
    long i = e * per + (long)blockIdx.x * blockDim.x + threadIdx.x;
    const float* src = (blockIdx.y == 0) ? w1 : (blockIdx.y == 1) ? w3 : w2;
    __half* dst = (blockIdx.y == 0) ? w1f : (blockIdx.y == 1) ? w3f : w2f;
    float4 v = ((const float4*)src)[i];
    union { uint2 u; __half h[4]; } p;
    p.h[0] = __float2half_rn(v.x);
    p.h[1] = __float2half_rn(v.y);
    p.h[2] = __float2half_rn(v.z);
    p.h[3] = __float2half_rn(v.w);
    ((uint2*)dst)[i] = p.u;
}

// ---------------------------------------------------------------------------
// Layout constants (BK=32, swizzled, no padding) — round-8 measured-good
// ---------------------------------------------------------------------------
#define BK 32
#define A_ARR 8192                     // 128 rows x 64B
#define FB_ARR 4096                    // 32 rows x 128B
#define F_STAGE (A_ARR + 2*FB_ARR)     // 16384
#define F_SMEM  (3 * F_STAGE)          // 49152
#define GB_ARR 8192                    // 32 rows x 256B
#define G_STAGE (A_ARR + GB_ARR)       // 16384
#define G_SMEM  (3 * G_STAGE)          // 49152

__device__ __forceinline__ uint32_t a_off(int row, int q) {
    return (uint32_t)(row * 64 + ((q ^ ((row >> 1) & 3)) << 4));
}
__device__ __forceinline__ uint32_t fb_off(int row, int c) {
    return (uint32_t)(row * 128 + ((c ^ (row & 7)) << 4));
}
__device__ __forceinline__ uint32_t gb_off(int row, int c) {
    return (uint32_t)(row * 256 + ((c ^ (row & 7)) << 4));
}

// ===========================================================================
// FUSED: a = x@W1, b = x@W3; h = gelu(a)*b -> fp16
// CTA 128m x 64n x 2 outputs, 8 warps: out_sel=wid>>2; wm=(wid&3)>>1, wn=wid&1.
// BK=32, 3-stage, one __syncthreads per chunk, 2 CTAs/SM.
// ===========================================================================
__device__ __forceinline__ void f_load_stage(
    uint32_t st,
    const __half* __restrict__ Af,
    const __half* __restrict__ B1, const __half* __restrict__ B3,
    long aRow0, long wBase, int n0, int kb, int tid)
{
#pragma unroll
    for (int j = 0; j < 2; j++) {        // A: 128 rows x 4 chunks
        int i = tid + j * 256;
        int row = (i >> 2) & 127, c16 = i & 3;
        CP_ASYNC16(st + a_off(row, c16), Af + (aRow0 + row) * (long)D_ + kb + c16 * 8);
    }
#pragma unroll
    for (int j = 0; j < 2; j++) {        // B: 2 arrays x 32 rows x 8 chunks
        int i = tid + j * 256;
        int arr = i >> 8, row = (i >> 3) & 31, c16 = i & 7;
        uint32_t s = st + A_ARR + arr * FB_ARR + fb_off(row, c16);
        const __half* g = (arr ? B3 : B1)
            + wBase + (long)(kb + row) * F_ + n0 + c16 * 8;
        CP_ASYNC16(s, g);
    }
}

__global__ __launch_bounds__(256, 2)
void fused_gemm12_kernel(const __half* __restrict__ Af,
                         const __half* __restrict__ B1,
                         const __half* __restrict__ B3,
                         const int* __restrict__ langs,
                         __half* __restrict__ outH)
{
    extern __shared__ char smem[];
    const uint32_t sbase = smem_to_u32(smem);

    const int tid = threadIdx.x;
    const int wid = tid >> 5;
    const int lane = tid & 31;
    const int out_sel = wid >> 2;          // 0: W1(a), 1: W3(b)
    const int w4 = wid & 3;
    const int wm = w4 >> 1;
    const int wn = w4 & 1;

    const int bz = blockIdx.z;
    const int m0 = blockIdx.y * 128;
    const int n0 = blockIdx.x * 64;

    const int lang = langs[bz];
    int e = lang - 4; if (e < 0) e = 0; if (e > 7) e = 7;

    const long aRow0 = (long)bz * S_ + m0;
    const long wBase = (long)e * D_ * F_;
    const int NC = D_ / BK;    // 32

    float acc[4][4][4];
#pragma unroll
    for (int i = 0; i < 4; i++)
#pragma unroll
        for (int j = 0; j < 4; j++)
#pragma unroll
            for (int q = 0; q < 4; q++) acc[i][j][q] = 0.0f;

    f_load_stage(sbase, Af, B1, B3, aRow0, wBase, n0, 0, tid);
    CP_COMMIT();
    f_load_stage(sbase + F_STAGE, Af, B1, B3, aRow0, wBase, n0, BK, tid);
    CP_COMMIT();

    const uint32_t stBoff = A_ARR + out_sel * FB_ARR;
    int sIdx = 0, sNext = 2;

    for (int c = 0; c < NC; ++c) {
        CP_WAIT1();
        __syncthreads();
        if (c + 2 < NC)
            f_load_stage(sbase + sNext * F_STAGE, Af, B1, B3,
                         aRow0, wBase, n0, (c + 2) * BK, tid);
        CP_COMMIT();

        const uint32_t st = sbase + sIdx * F_STAGE;
        const uint32_t stB = st + stBoff;
#pragma unroll
        for (int ks = 0; ks < 2; ks++) {
            uint32_t bf[4][2];
#pragma unroll
            for (int half = 0; half < 2; half++) {
                int brow = ks * 16 + (lane & 15);
                int bc = wn * 4 + half * 2 + (lane >> 4);
                uint32_t r0, r1, r2, r3;
                ldsm_x4_t(r0, r1, r2, r3, stB + fb_off(brow, bc));
                bf[half * 2][0] = r0; bf[half * 2][1] = r1;
                bf[half * 2 + 1][0] = r2; bf[half * 2 + 1][1] = r3;
            }
#pragma unroll
            for (int mt = 0; mt < 4; mt++) {
                int row = wm * 64 + mt * 16 + (lane & 15);
                uint32_t off = a_off(row, ks * 2 + (lane >> 4));
                uint32_t af[4];
                ldsm_x4(af[0], af[1], af[2], af[3], st + off);
#pragma unroll
                for (int nt = 0; nt < 4; nt++)
                    mma_16816(acc[mt][nt], af, bf[nt]);
            }
        }
        sIdx = (sIdx == 2) ? 0 : sIdx + 1;
        sNext = (sNext == 2) ? 0 : sNext + 1;
    }

    // --- epilogue: a-warps dump acc to smem; b-warps apply gelu(a)*b ---
    __syncthreads();
    float* ex = (float*)smem;              // 32 KB needed, 48 KB available
    if (out_sel == 0) {
#pragma unroll
        for (int mt = 0; mt < 4; mt++)
#pragma unroll
            for (int nt = 0; nt < 4; nt++)
#pragma unroll
                for (int q = 0; q < 4; q++) {
                    int i = (mt * 4 + nt) * 4 + q;
                    ex[w4 * 2048 + i * 32 + lane] = acc[mt][nt][q];
                }
    }
    __syncthreads();
    if (out_sel == 1) {
        const int qr = lane >> 2;
        const int qc = (lane & 3) * 2;
#pragma unroll
        for (int mt = 0; mt < 4; mt++) {
#pragma unroll
            for (int half = 0; half < 2; half++) {
                const int gm = m0 + wm * 64 + mt * 16 + qr + half * 8;
                const long rowBase = ((long)bz * S_ + gm) * (long)F_;
#pragma unroll
                for (int nt = 0; nt < 4; nt++) {
                    const int gn = n0 + wn * 32 + nt * 8 + qc;
                    const long idx = rowBase + gn;
                    float b0 = acc[mt][nt][half * 2 + 0];
                    float b1 = acc[mt][nt][half * 2 + 1];
                    int i0 = (mt * 4 + nt) * 4 + half * 2;
                    float a0 = ex[w4 * 2048 + i0 * 32 + lane];
                    float a1 = ex[w4 * 2048 + (i0 + 1) * 32 + lane];
                    float g0 = 0.5f * a0 * (1.0f + erff(a0 * 0.70710678118654752f));
                    float g1 = 0.5f * a1 * (1.0f + erff(a1 * 0.70710678118654752f));
                    union { uint32_t u; __half h[2]; } uh;
                    uh.h[0] = __float2half_rn(g0 * b0);
                    uh.h[1] = __float2half_rn(g1 * b1);
                    *(uint32_t*)(outH + idx) = uh.u;
                }
            }
        }
    }
}

// ===========================================================================
// GEMM3 (split-K=2): out += rw * (h[.., Khalf] @ W2[Khalf, ..]) via REDG
// CTA 128m x 128n, 8 warps 2m x 4n of 64x32.  BK=32.
// ===========================================================================
__device__ __forceinline__ void g_load_stage(
    uint32_t st,
    const __half* __restrict__ Af, const __half* __restrict__ Bf,
    long aRow0, long wBase, int n0, int kb, int tid)
{
#pragma unroll
    for (int j = 0; j < 2; j++) {
        int i = tid + j * 256;
        int row = (i >> 2) & 127, c16 = i & 3;
        CP_ASYNC16(st + a_off(row, c16), Af + (aRow0 + row) * (long)F_ + kb + c16 * 8);
    }
#pragma unroll
    for (int j = 0; j < 2; j++) {
        int i = tid + j * 256;
        int row = (i >> 4) & 31, c16 = i & 15;
        uint32_t s = st + A_ARR + gb_off(row, c16);
        CP_ASYNC16(s, Bf + wBase + (long)(kb + row) * D_ + n0 + c16 * 8);
    }
}

__global__ __launch_bounds__(256, 2)
void gemm3_kernel(const __half* __restrict__ Af,
                  const __half* __restrict__ Bf,
                  const int* __restrict__ langs,
                  float* __restrict__ out)
{
    extern __shared__ char smem[];
    const uint32_t sbase = smem_to_u32(smem);

    const int tid = threadIdx.x;
    const int wid = tid >> 5;
    const int lane = tid & 31;
    const int wm = wid >> 2;
    const int wn = wid & 3;

    const int z = blockIdx.z;
    const int bz = z >> 1;
    const int kh = z & 1;
    const int m0 = blockIdx.y * 128;
    const int n0 = blockIdx.x * 128;

    const int lang = langs[bz];
    int e = lang - 4; if (e < 0) e = 0; if (e > 7) e = 7;
    const int cnt = (lang > 3) ? 1 : 0;
    const float rw = (cnt == 0) ? 1.0f : (1.0f / (float)cnt);

    const long aRow0 = (long)bz * S_ + m0;
    const long wBase = (long)e * F_ * D_;
    const int kBase = kh * (F_ / 2);
    const int NC = (F_ / 2) / BK;         // 64

    float acc[4][4][4];
#pragma unroll
    for (int i = 0; i < 4; i++)
#pragma unroll
        for (int j = 0; j < 4; j++)
#pragma unroll
            for (int q = 0; q < 4; q++) acc[i][j][q] = 0.0f;

    g_load_stage(sbase, Af, Bf, aRow0, wBase, n0, kBase, tid);
    CP_COMMIT();
    g_load_stage(sbase + G_STAGE, Af, Bf, aRow0, wBase, n0, kBase + BK, tid);
    CP_COMMIT();

    int sIdx = 0, sNext = 2;

    for (int c = 0; c < NC; ++c) {
        CP_WAIT1();
        __syncthreads();
        if (c + 2 < NC)
            g_load_stage(sbase + sNext * G_STAGE, Af, Bf,
                         aRow0, wBase, n0, kBase + (c + 2) * BK, tid);
        CP_COMMIT();

        const uint32_t st = sbase + sIdx * G_STAGE;
        const uint32_t stB = st + A_ARR;
#pragma unroll
        for (int ks = 0; ks < 2; ks++) {
            uint32_t bf[4][2];
#pragma unroll
            for (int half = 0; half < 2; half++) {
                int brow = ks * 16 + (lane & 15);
                int bc = wn * 4 + half * 2 + (lane >> 4);
                uint32_t r0, r1, r2, r3;
                ldsm_x4_t(r0, r1, r2, r3, stB + gb_off(brow, bc));
                bf[half * 2][0] = r0; bf[half * 2][1] = r1;
                bf[half * 2 + 1][0] = r2; bf[half * 2 + 1][1] = r3;
            }
#pragma unroll
            for (int mt = 0; mt < 4; mt++) {
                int row = wm * 64 + mt * 16 + (lane & 15);
                uint32_t off = a_off(row, ks * 2 + (lane >> 4));
                uint32_t af[4];
                ldsm_x4(af[0], af[1], af[2], af[3], st + off);
#pragma unroll
                for (int nt = 0; nt < 4; nt++)
                    mma_16816(acc[mt][nt], af, bf[nt]);
            }
        }
        sIdx = (sIdx == 2) ? 0 : sIdx + 1;
        sNext = (sNext == 2) ? 0 : sNext + 1;
    }

    // epilogue: REDG-accumulate rw-scaled partials into pre-zeroed out
    const int qr = lane >> 2;
    const int qc = (lane & 3) * 2;
#pragma unroll
    for (int mt = 0; mt < 4; mt++) {
#pragma unroll
        for (int half = 0; half < 2; half++) {
            const int gm = m0 + wm * 64 + mt * 16 + qr + half * 8;
            const long rowBase = ((long)bz * S_ + gm) * (long)D_;
#pragma unroll
            for (int nt = 0; nt < 4; nt++) {
                const int gn = n0 + wn * 32 + nt * 8 + qc;
                atomicAdd(out + rowBase + gn, acc[mt][nt][half * 2] * rw);
                atomicAdd(out + rowBase + gn + 1, acc[mt][nt][half * 2 + 1] * rw);
            }
        }
    }
}

// ---------------------------------------------------------------------------
// Launch
// ---------------------------------------------------------------------------
extern "C" void kernel_launch(void* const* d_in, const int* in_sizes, int n_in,
                              void* d_out, int out_size)
{
    const float* x     = (const float*)d_in[0];
    const float* w1    = (const float*)d_in[1];
    const float* w2    = (const float*)d_in[2];
    const float* w3    = (const float*)d_in[3];
    const int*   langs = (const int*)  d_in[4];
    float* out = (float*)d_out;

    __half *xf, *w1f, *w3f, *w2f, *hf;
    cudaGetSymbolAddress((void**)&xf,  g_xf);
    cudaGetSymbolAddress((void**)&w1f, g_w1f);
    cudaGetSymbolAddress((void**)&w3f, g_w3f);
    cudaGetSymbolAddress((void**)&w2f, g_w2f);
    cudaGetSymbolAddress((void**)&hf,  g_hf);

    cudaFuncSetAttribute(fused_gemm12_kernel,
                         cudaFuncAttributeMaxDynamicSharedMemorySize, F_SMEM);
    cudaFuncSetAttribute(gemm3_kernel,
                         cudaFuncAttributeMaxDynamicSharedMemorySize, G_SMEM);

    // 0) zero output (REDG accumulation target)
    {
        long n4 = (long)B_ * S_ * D_ / 4;
        zero_kernel<<<(unsigned)(n4 / 256), 256>>>((float4*)out, n4);
    }
    // 1) prep: fp16 conversions (weights expert-gated)
    {
        long nx = (long)B_ * S_ * D_ / 4;
        convert_x_kernel<<<(unsigned)(nx / 256), 256>>>(x, xf, nx);
        unsigned wb = (unsigned)(((long)D_ * F_ / 4) / 256);
        dim3 gw(wb, 3, E_);
        convert_w_kernel<<<gw, 256>>>(w1, w3, w2, w1f, w3f, w2f, langs);
    }
    // 2) fused GEMM1+GEMM2 + GLU -> h (fp16)
    {
        dim3 grid(F_ / 64, S_ / 128, B_);
        fused_gemm12_kernel<<<grid, 256, F_SMEM>>>(xf, w1f, w3f, langs, hf);
    }
    // 3) GEMM3 split-K=2, REDG into out
    {
        dim3 grid(D_ / 128, S_ / 128, B_ * 2);
        gemm3_kernel<<<grid, 256, G_SMEM>>>(hf, w2f, langs, out);
    }
}

// round 12
// speedup vs baseline: 1.4657x; 1.0220x over previous
#include <cuda_runtime.h>
#include <cuda_fp16.h>
#include <math.h>
#include <stdint.h>

// ---------------------------------------------------------------------------
#define B_ 8
#define S_ 2048
#define D_ 1024
#define F_ 4096
#define E_ 8

// ---------------------------------------------------------------------------
// Scratch (__device__ globals). Everything single fp16, K-major.
// ---------------------------------------------------------------------------
__device__ __half g_xf[(size_t)B_ * S_ * D_];
__device__ __half g_w1f[(size_t)E_ * D_ * F_];
__device__ __half g_w3f[(size_t)E_ * D_ * F_];
__device__ __half g_w2f[(size_t)E_ * F_ * D_];
__device__ __half g_hf[(size_t)B_ * S_ * F_];

// ---------------------------------------------------------------------------
// PTX helpers (base-target-safe)
// ---------------------------------------------------------------------------
__device__ __forceinline__ uint32_t smem_to_u32(const void* p) {
    uint32_t a;
    asm("{ .reg .u64 t; cvta.to.shared.u64 t, %1; cvt.u32.u64 %0, t; }" : "=r"(a) : "l"(p));
    return a;
}
#define CP_ASYNC16(saddr, gptr) \
    asm volatile("cp.async.cg.shared.global [%0], [%1], 16;" :: "r"(saddr), "l"(gptr))
#define CP_COMMIT()  asm volatile("cp.async.commit_group;" ::: "memory")
#define CP_WAIT2()   asm volatile("cp.async.wait_group 2;" ::: "memory")

__device__ __forceinline__ void ldsm_x4(uint32_t& r0, uint32_t& r1, uint32_t& r2,
                                        uint32_t& r3, uint32_t addr) {
    asm volatile("ldmatrix.sync.aligned.m8n8.x4.shared.b16 {%0,%1,%2,%3}, [%4];"
                 : "=r"(r0), "=r"(r1), "=r"(r2), "=r"(r3) : "r"(addr));
}
__device__ __forceinline__ void ldsm_x4_t(uint32_t& r0, uint32_t& r1, uint32_t& r2,
                                          uint32_t& r3, uint32_t addr) {
    asm volatile("ldmatrix.sync.aligned.m8n8.x4.trans.shared.b16 {%0,%1,%2,%3}, [%4];"
                 : "=r"(r0), "=r"(r1), "=r"(r2), "=r"(r3) : "r"(addr));
}
__device__ __forceinline__ void mma_16816(float* d, const uint32_t* a, const uint32_t* b) {
    asm volatile(
        "mma.sync.aligned.m16n8k16.row.col.f32.f16.f16.f32 "
        "{%0,%1,%2,%3}, {%4,%5,%6,%7}, {%8,%9}, {%0,%1,%2,%3};"
        : "+f"(d[0]), "+f"(d[1]), "+f"(d[2]), "+f"(d[3])
        : "r"(a[0]), "r"(a[1]), "r"(a[2]), "r"(a[3]), "r"(b[0]), "r"(b[1]));
}

// ---------------------------------------------------------------------------
// Prep kernels
// ---------------------------------------------------------------------------
__global__ __launch_bounds__(256)
void zero_kernel(float4* __restrict__ out, long n4)
{
    long i = (long)blockIdx.x * blockDim.x + threadIdx.x;
    if (i < n4) out[i] = make_float4(0.f, 0.f, 0.f, 0.f);
}

__global__ __launch_bounds__(256)
void convert_x_kernel(const float* __restrict__ src, __half* __restrict__ dst, long n4)
{
    long i = (long)blockIdx.x * blockDim.x + threadIdx.x;
    if (i >= n4) return;
    float4 v = ((const float4*)src)[i];
    union { uint2 u; __half h[4]; } p;
    p.h[0] = __float2half_rn(v.x);
    p.h[1] = __float2half_rn(v.y);
    p.h[2] = __float2half_rn(v.z);
    p.h[3] = __float2half_rn(v.w);
    ((uint2*)dst)[i] = p.u;
}

// weight conversion, expert-gated.  grid: (blocksPerExpert, 3, E_)
__global__ __launch_bounds__(256)
void convert_w_kernel(const float* __restrict__ w1,
                      const float* __restrict__ w3,
                      const float* __restrict__ w2,
                      __half* __restrict__ w1f,
                      __half* __restrict__ w3f,
                      __half* __restrict__ w2f,
                      const int* __restrict__ langs)
{
    const int e = blockIdx.z;
    int used = 0;
#pragma unroll
    for (int b = 0; b < B_; b++)
        if (langs[b] - 4 == e) used = 1;
    if (!used) return;
    const long per = (long)D_ * F_ / 4;
    long i = e * per + (long)blockIdx.x * blockDim.x + threadIdx.x;
    const float* src = (blockIdx.y == 0) ? w1 : (blockIdx.y == 1) ? w3 : w2;
    __half* dst = (blockIdx.y == 0) ? w1f : (blockIdx.y == 1) ? w3f : w2f;
    float4 v = ((const float4*)src)[i];
    union { uint2 u; __half h[4]; } p;
    p.h[0] = __float2half_rn(v.x);
    p.h[1] = __float2half_rn(v.y);
    p.h[2] = __float2half_rn(v.z);
    p.h[3] = __float2half_rn(v.w);
    ((uint2*)dst)[i] = p.u;
}

// ---------------------------------------------------------------------------
// Layout constants (BK=32, swizzled, 4 stages)
// ---------------------------------------------------------------------------
#define BK 32
#define A_ARR 8192                     // 128 rows x 64B
#define FB_ARR 4096                    // 32 rows x 128B
#define F_STAGE (A_ARR + 2*FB_ARR)     // 16384
#define F_SMEM  (4 * F_STAGE)          // 65536
#define GB_ARR 8192                    // 32 rows x 256B
#define G_STAGE (A_ARR + GB_ARR)       // 16384
#define G_SMEM  (4 * G_STAGE)          // 65536

__device__ __forceinline__ uint32_t a_off(int row, int q) {
    return (uint32_t)(row * 64 + ((q ^ ((row >> 1) & 3)) << 4));
}
__device__ __forceinline__ uint32_t fb_off(int row, int c) {
    return (uint32_t)(row * 128 + ((c ^ (row & 7)) << 4));
}
__device__ __forceinline__ uint32_t gb_off(int row, int c) {
    return (uint32_t)(row * 256 + ((c ^ (row & 7)) << 4));
}

// ===========================================================================
// FUSED: a = x@W1, b = x@W3; h = gelu(a)*b -> fp16
// CTA 128m x 64n x 2 outputs, 8 warps.  BK=32, 4-stage, pointer-hoisted loads.
// ===========================================================================
__global__ __launch_bounds__(256, 2)
void fused_gemm12_kernel(const __half* __restrict__ Af,
                         const __half* __restrict__ B1,
                         const __half* __restrict__ B3,
                         const int* __restrict__ langs,
                         __half* __restrict__ outH)
{
    extern __shared__ char smem[];
    const uint32_t sbase = smem_to_u32(smem);

    const int tid = threadIdx.x;
    const int wid = tid >> 5;
    const int lane = tid & 31;
    const int out_sel = wid >> 2;          // 0: W1(a), 1: W3(b)
    const int w4 = wid & 3;
    const int wm = w4 >> 1;
    const int wn = w4 & 1;

    const int bz = blockIdx.z;
    const int m0 = blockIdx.y * 128;
    const int n0 = blockIdx.x * 64;

    const int lang = langs[bz];
    int e = lang - 4; if (e < 0) e = 0; if (e > 7) e = 7;

    const long aRow0 = (long)bz * S_ + m0;
    const long wBase = (long)e * D_ * F_;
    const int NC = D_ / BK;    // 32

    // ---- hoisted per-thread load pointers + smem offsets ----
    const int ar = tid >> 2;               // A row 0..63 (second row = +64)
    const int ac = tid & 3;                // A 16B chunk 0..3
    const __half* pA = Af + (aRow0 + ar) * (long)D_ + ac * 8;
    const uint32_t sA0 = a_off(ar, ac);
    const uint32_t sA1 = a_off(ar + 64, ac);

    const int br = tid >> 3;               // B k-row 0..31
    const int bc8 = tid & 7;               // B 16B chunk 0..7
    const __half* pB1 = B1 + wBase + (long)br * F_ + n0 + bc8 * 8;
    const __half* pB3 = B3 + wBase + (long)br * F_ + n0 + bc8 * 8;
    const uint32_t sB = A_ARR + fb_off(br, bc8);

    float acc[4][4][4];
#pragma unroll
    for (int i = 0; i < 4; i++)
#pragma unroll
        for (int j = 0; j < 4; j++)
#pragma unroll
            for (int q = 0; q < 4; q++) acc[i][j][q] = 0.0f;

    // prologue: stages 0..2
#pragma unroll
    for (int s = 0; s < 3; s++) {
        const uint32_t st = sbase + s * F_STAGE;
        CP_ASYNC16(st + sA0, pA);
        CP_ASYNC16(st + sA1, pA + (long)64 * D_);
        CP_ASYNC16(st + sB, pB1);
        CP_ASYNC16(st + sB + FB_ARR, pB3);
        CP_COMMIT();
        pA += BK; pB1 += (long)BK * F_; pB3 += (long)BK * F_;
    }

    const uint32_t stBoff = A_ARR + out_sel * FB_ARR;

    for (int c = 0; c < NC; ++c) {
        CP_WAIT2();
        __syncthreads();
        if (c + 3 < NC) {
            const uint32_t st = sbase + ((c + 3) & 3) * F_STAGE;
            CP_ASYNC16(st + sA0, pA);
            CP_ASYNC16(st + sA1, pA + (long)64 * D_);
            CP_ASYNC16(st + sB, pB1);
            CP_ASYNC16(st + sB + FB_ARR, pB3);
            pA += BK; pB1 += (long)BK * F_; pB3 += (long)BK * F_;
        }
        CP_COMMIT();

        const uint32_t st = sbase + (c & 3) * F_STAGE;
        const uint32_t stB = st + stBoff;
#pragma unroll
        for (int ks = 0; ks < 2; ks++) {
            uint32_t bf[4][2];
#pragma unroll
            for (int half = 0; half < 2; half++) {
                int brow = ks * 16 + (lane & 15);
                int bc = wn * 4 + half * 2 + (lane >> 4);
                uint32_t r0, r1, r2, r3;
                ldsm_x4_t(r0, r1, r2, r3, stB + fb_off(brow, bc));
                bf[half * 2][0] = r0; bf[half * 2][1] = r1;
                bf[half * 2 + 1][0] = r2; bf[half * 2 + 1][1] = r3;
            }
#pragma unroll
            for (int mt = 0; mt < 4; mt++) {
                int row = wm * 64 + mt * 16 + (lane & 15);
                uint32_t off = a_off(row, ks * 2 + (lane >> 4));
                uint32_t af[4];
                ldsm_x4(af[0], af[1], af[2], af[3], st + off);
#pragma unroll
                for (int nt = 0; nt < 4; nt++)
                    mma_16816(acc[mt][nt], af, bf[nt]);
            }
        }
    }

    // --- epilogue: a-warps dump acc to smem; b-warps apply gelu(a)*b ---
    __syncthreads();
    float* ex = (float*)smem;
    if (out_sel == 0) {
#pragma unroll
        for (int mt = 0; mt < 4; mt++)
#pragma unroll
            for (int nt = 0; nt < 4; nt++)
#pragma unroll
                for (int q = 0; q < 4; q++) {
                    int i = (mt * 4 + nt) * 4 + q;
                    ex[w4 * 2048 + i * 32 + lane] = acc[mt][nt][q];
                }
    }
    __syncthreads();
    if (out_sel == 1) {
        const int qr = lane >> 2;
        const int qc = (lane & 3) * 2;
#pragma unroll
        for (int mt = 0; mt < 4; mt++) {
#pragma unroll
            for (int half = 0; half < 2; half++) {
                const int gm = m0 + wm * 64 + mt * 16 + qr + half * 8;
                const long rowBase = ((long)bz * S_ + gm) * (long)F_;
#pragma unroll
                for (int nt = 0; nt < 4; nt++) {
                    const int gn = n0 + wn * 32 + nt * 8 + qc;
                    const long idx = rowBase + gn;
                    float b0 = acc[mt][nt][half * 2 + 0];
                    float b1 = acc[mt][nt][half * 2 + 1];
                    int i0 = (mt * 4 + nt) * 4 + half * 2;
                    float a0 = ex[w4 * 2048 + i0 * 32 + lane];
                    float a1 = ex[w4 * 2048 + (i0 + 1) * 32 + lane];
                    float g0 = 0.5f * a0 * (1.0f + erff(a0 * 0.70710678118654752f));
                    float g1 = 0.5f * a1 * (1.0f + erff(a1 * 0.70710678118654752f));
                    union { uint32_t u; __half h[2]; } uh;
                    uh.h[0] = __float2half_rn(g0 * b0);
                    uh.h[1] = __float2half_rn(g1 * b1);
                    *(uint32_t*)(outH + idx) = uh.u;
                }
            }
        }
    }
}

// ===========================================================================
// GEMM3 (split-K=2): out += rw * (h[.., Khalf] @ W2[Khalf, ..]) via REDG
// CTA 128m x 128n, 8 warps 2m x 4n.  BK=32, 4-stage, pointer-hoisted loads.
// ===========================================================================
__global__ __launch_bounds__(256, 2)
void gemm3_kernel(const __half* __restrict__ Af,
                  const __half* __restrict__ Bf,
                  const int* __restrict__ langs,
                  float* __restrict__ out)
{
    extern __shared__ char smem[];
    const uint32_t sbase = smem_to_u32(smem);

    const int tid = threadIdx.x;
    const int wid = tid >> 5;
    const int lane = tid & 31;
    const int wm = wid >> 2;
    const int wn = wid & 3;

    const int z = blockIdx.z;
    const int bz = z >> 1;
    const int kh = z & 1;
    const int m0 = blockIdx.y * 128;
    const int n0 = blockIdx.x * 128;

    const int lang = langs[bz];
    int e = lang - 4; if (e < 0) e = 0; if (e > 7) e = 7;
    const int cnt = (lang > 3) ? 1 : 0;
    const float rw = (cnt == 0) ? 1.0f : (1.0f / (float)cnt);

    const long aRow0 = (long)bz * S_ + m0;
    const long wBase = (long)e * F_ * D_;
    const int kBase = kh * (F_ / 2);
    const int NC = (F_ / 2) / BK;         // 64

    // ---- hoisted per-thread load pointers + smem offsets ----
    const int ar = tid >> 2;
    const int ac = tid & 3;
    const __half* pA = Af + (aRow0 + ar) * (long)F_ + kBase + ac * 8;
    const uint32_t sA0 = a_off(ar, ac);
    const uint32_t sA1 = a_off(ar + 64, ac);

    const int br = tid >> 4;              // 0..15 (second row = +16)
    const int bc16 = tid & 15;
    const __half* pB = Bf + wBase + (long)(kBase + br) * D_ + n0 + bc16 * 8;
    const uint32_t sB0 = A_ARR + gb_off(br, bc16);
    const uint32_t sB1 = A_ARR + gb_off(br + 16, bc16);

    float acc[4][4][4];
#pragma unroll
    for (int i = 0; i < 4; i++)
#pragma unroll
        for (int j = 0; j < 4; j++)
#pragma unroll
            for (int q = 0; q < 4; q++) acc[i][j][q] = 0.0f;

#pragma unroll
    for (int s = 0; s < 3; s++) {
        const uint32_t st = sbase + s * G_STAGE;
        CP_ASYNC16(st + sA0, pA);
        CP_ASYNC16(st + sA1, pA + (long)64 * F_);
        CP_ASYNC16(st + sB0, pB);
        CP_ASYNC16(st + sB1, pB + (long)16 * D_);
        CP_COMMIT();
        pA += BK; pB += (long)BK * D_;
    }

    for (int c = 0; c < NC; ++c) {
        CP_WAIT2();
        __syncthreads();
        if (c + 3 < NC) {
            const uint32_t st = sbase + ((c + 3) & 3) * G_STAGE;
            CP_ASYNC16(st + sA0, pA);
            CP_ASYNC16(st + sA1, pA + (long)64 * F_);
            CP_ASYNC16(st + sB0, pB);
            CP_ASYNC16(st + sB1, pB + (long)16 * D_);
            pA += BK; pB += (long)BK * D_;
        }
        CP_COMMIT();

        const uint32_t st = sbase + (c & 3) * G_STAGE;
        const uint32_t stB = st + A_ARR;
#pragma unroll
        for (int ks = 0; ks < 2; ks++) {
            uint32_t bf[4][2];
#pragma unroll
            for (int half = 0; half < 2; half++) {
                int brow = ks * 16 + (lane & 15);
                int bc = wn * 4 + half * 2 + (lane >> 4);
                uint32_t r0, r1, r2, r3;
                ldsm_x4_t(r0, r1, r2, r3, stB + gb_off(brow, bc));
                bf[half * 2][0] = r0; bf[half * 2][1] = r1;
                bf[half * 2 + 1][0] = r2; bf[half * 2 + 1][1] = r3;
            }
#pragma unroll
            for (int mt = 0; mt < 4; mt++) {
                int row = wm * 64 + mt * 16 + (lane & 15);
                uint32_t off = a_off(row, ks * 2 + (lane >> 4));
                uint32_t af[4];
                ldsm_x4(af[0], af[1], af[2], af[3], st + off);
#pragma unroll
                for (int nt = 0; nt < 4; nt++)
                    mma_16816(acc[mt][nt], af, bf[nt]);
            }
        }
    }

    // epilogue: REDG-accumulate rw-scaled partials into pre-zeroed out
    const int qr = lane >> 2;
    const int qc = (lane & 3) * 2;
#pragma unroll
    for (int mt = 0; mt < 4; mt++) {
#pragma unroll
        for (int half = 0; half < 2; half++) {
            const int gm = m0 + wm * 64 + mt * 16 + qr + half * 8;
            const long rowBase = ((long)bz * S_ + gm) * (long)D_;
#pragma unroll
            for (int nt = 0; nt < 4; nt++) {
                const int gn = n0 + wn * 32 + nt * 8 + qc;
                atomicAdd(out + rowBase + gn, acc[mt][nt][half * 2] * rw);
                atomicAdd(out + rowBase + gn + 1, acc[mt][nt][half * 2 + 1] * rw);
            }
        }
    }
}

// ---------------------------------------------------------------------------
// Launch
// ---------------------------------------------------------------------------
extern "C" void kernel_launch(void* const* d_in, const int* in_sizes, int n_in,
                              void* d_out, int out_size)
{
    const float* x     = (const float*)d_in[0];
    const float* w1    = (const float*)d_in[1];
    const float* w2    = (const float*)d_in[2];
    const float* w3    = (const float*)d_in[3];
    const int*   langs = (const int*)  d_in[4];
    float* out = (float*)d_out;

    __half *xf, *w1f, *w3f, *w2f, *hf;
    cudaGetSymbolAddress((void**)&xf,  g_xf);
    cudaGetSymbolAddress((void**)&w1f, g_w1f);
    cudaGetSymbolAddress((void**)&w3f, g_w3f);
    cudaGetSymbolAddress((void**)&w2f, g_w2f);
    cudaGetSymbolAddress((void**)&hf,  g_hf);

    cudaFuncSetAttribute(fused_gemm12_kernel,
                         cudaFuncAttributeMaxDynamicSharedMemorySize, F_SMEM);
    cudaFuncSetAttribute(gemm3_kernel,
                         cudaFuncAttributeMaxDynamicSharedMemorySize, G_SMEM);

    // 0) zero output (REDG accumulation target)
    {
        long n4 = (long)B_ * S_ * D_ / 4;
        zero_kernel<<<(unsigned)(n4 / 256), 256>>>((float4*)out, n4);
    }
    // 1) prep: fp16 conversions (weights expert-gated)
    {
        long nx = (long)B_ * S_ * D_ / 4;
        convert_x_kernel<<<(unsigned)(nx / 256), 256>>>(x, xf, nx);
        unsigned wb = (unsigned)(((long)D_ * F_ / 4) / 256);
        dim3 gw(wb, 3, E_);
        convert_w_kernel<<<gw, 256>>>(w1, w3, w2, w1f, w3f, w2f, langs);
    }
    // 2) fused GEMM1+GEMM2 + GLU -> h (fp16)
    {
        dim3 grid(F_ / 64, S_ / 128, B_);
        fused_gemm12_kernel<<<grid, 256, F_SMEM>>>(xf, w1f, w3f, langs, hf);
    }
    // 3) GEMM3 split-K=2, REDG into out
    {
        dim3 grid(D_ / 128, S_ / 128, B_ * 2);
        gemm3_kernel<<<grid, 256, G_SMEM>>>(hf, w2f, langs, out);
    }
}

// round 13
// speedup vs baseline: 1.5650x; 1.0678x over previous
#include <cuda_runtime.h>
#include <cuda_fp16.h>
#include <math.h>
#include <stdint.h>

// ---------------------------------------------------------------------------
#define B_ 8
#define S_ 2048
#define D_ 1024
#define F_ 4096
#define E_ 8

// ---------------------------------------------------------------------------
// Scratch (__device__ globals). Everything single fp16, K-major.
// ---------------------------------------------------------------------------
__device__ __half g_xf[(size_t)B_ * S_ * D_];
__device__ __half g_w1f[(size_t)E_ * D_ * F_];
__device__ __half g_w3f[(size_t)E_ * D_ * F_];
__device__ __half g_w2f[(size_t)E_ * F_ * D_];
__device__ __half g_hf[(size_t)B_ * S_ * F_];

// ---------------------------------------------------------------------------
// PTX helpers (base-target-safe)
// ---------------------------------------------------------------------------
__device__ __forceinline__ uint32_t smem_to_u32(const void* p) {
    uint32_t a;
    asm("{ .reg .u64 t; cvta.to.shared.u64 t, %1; cvt.u32.u64 %0, t; }" : "=r"(a) : "l"(p));
    return a;
}
#define CP_ASYNC16(saddr, gptr) \
    asm volatile("cp.async.cg.shared.global [%0], [%1], 16;" :: "r"(saddr), "l"(gptr))
#define CP_COMMIT()  asm volatile("cp.async.commit_group;" ::: "memory")
#define CP_WAIT2()   asm volatile("cp.async.wait_group 2;" ::: "memory")

__device__ __forceinline__ void ldsm_x4(uint32_t& r0, uint32_t& r1, uint32_t& r2,
                                        uint32_t& r3, uint32_t addr) {
    asm volatile("ldmatrix.sync.aligned.m8n8.x4.shared.b16 {%0,%1,%2,%3}, [%4];"
                 : "=r"(r0), "=r"(r1), "=r"(r2), "=r"(r3) : "r"(addr));
}
__device__ __forceinline__ void ldsm_x4_t(uint32_t& r0, uint32_t& r1, uint32_t& r2,
                                          uint32_t& r3, uint32_t addr) {
    asm volatile("ldmatrix.sync.aligned.m8n8.x4.trans.shared.b16 {%0,%1,%2,%3}, [%4];"
                 : "=r"(r0), "=r"(r1), "=r"(r2), "=r"(r3) : "r"(addr));
}
__device__ __forceinline__ void mma_16816(float* d, const uint32_t* a, const uint32_t* b) {
    asm volatile(
        "mma.sync.aligned.m16n8k16.row.col.f32.f16.f16.f32 "
        "{%0,%1,%2,%3}, {%4,%5,%6,%7}, {%8,%9}, {%0,%1,%2,%3};"
        : "+f"(d[0]), "+f"(d[1]), "+f"(d[2]), "+f"(d[3])
        : "r"(a[0]), "r"(a[1]), "r"(a[2]), "r"(a[3]), "r"(b[0]), "r"(b[1]));
}

// ---------------------------------------------------------------------------
// Prep kernels (2 float4 per thread, dual-stream indexing)
// ---------------------------------------------------------------------------
__global__ __launch_bounds__(256)
void zero_kernel(float4* __restrict__ out, long n4)
{
    long half = n4 >> 1;
    long i = (long)blockIdx.x * blockDim.x + threadIdx.x;
    if (i < half) {
        out[i] = make_float4(0.f, 0.f, 0.f, 0.f);
        out[i + half] = make_float4(0.f, 0.f, 0.f, 0.f);
    }
}

__device__ __forceinline__ uint2 cvt4(float4 v) {
    union { uint2 u; __half h[4]; } p;
    p.h[0] = __float2half_rn(v.x);
    p.h[1] = __float2half_rn(v.y);
    p.h[2] = __float2half_rn(v.z);
    p.h[3] = __float2half_rn(v.w);
    return p.u;
}

__global__ __launch_bounds__(256)
void convert_x_kernel(const float* __restrict__ src, __half* __restrict__ dst, long n4)
{
    long half = n4 >> 1;
    long i = (long)blockIdx.x * blockDim.x + threadIdx.x;
    if (i >= half) return;
    ((uint2*)dst)[i] = cvt4(((const float4*)src)[i]);
    ((uint2*)dst)[i + half] = cvt4(((const float4*)src)[i + half]);
}

// weight conversion, expert-gated.  grid: (blocksPerExpert/2, 3, E_)
__global__ __launch_bounds__(256)
void convert_w_kernel(const float* __restrict__ w1,
                      const float* __restrict__ w3,
                      const float* __restrict__ w2,
                      __half* __restrict__ w1f,
                      __half* __restrict__ w3f,
                      __half* __restrict__ w2f,
                      const int* __restrict__ langs)
{
    const int e = blockIdx.z;
    int used = 0;
#pragma unroll
    for (int b = 0; b < B_; b++)
        if (langs[b] - 4 == e) used = 1;
    if (!used) return;
    const long per = (long)D_ * F_ / 4;          // float4 per expert
    const long half = per >> 1;
    long j = (long)blockIdx.x * blockDim.x + threadIdx.x;
    if (j >= half) return;
    long i = e * per + j;
    const float* src = (blockIdx.y == 0) ? w1 : (blockIdx.y == 1) ? w3 : w2;
    __half* dst = (blockIdx.y == 0) ? w1f : (blockIdx.y == 1) ? w3f : w2f;
    ((uint2*)dst)[i] = cvt4(((const float4*)src)[i]);
    ((uint2*)dst)[i + half] = cvt4(((const float4*)src)[i + half]);
}

// ---------------------------------------------------------------------------
// Layout constants (BK=32, swizzled, 4 stages)
// ---------------------------------------------------------------------------
#define BK 32
#define A_ARR 8192                     // 128 rows x 64B
#define FB_ARR 4096                    // 32 rows x 128B
#define F_STAGE (A_ARR + 2*FB_ARR)     // 16384
#define F_SMEM  (4 * F_STAGE)          // 65536
#define GB_ARR 8192                    // 32 rows x 256B
#define G_STAGE (A_ARR + GB_ARR)       // 16384
#define G_SMEM  (4 * G_STAGE)          // 65536

__device__ __forceinline__ uint32_t a_off(int row, int q) {
    return (uint32_t)(row * 64 + ((q ^ ((row >> 1) & 3)) << 4));
}
__device__ __forceinline__ uint32_t fb_off(int row, int c) {
    return (uint32_t)(row * 128 + ((c ^ (row & 7)) << 4));
}
__device__ __forceinline__ uint32_t gb_off(int row, int c) {
    return (uint32_t)(row * 256 + ((c ^ (row & 7)) << 4));
}

// ===========================================================================
// FUSED: a = x@W1, b = x@W3; h = gelu(a)*b -> fp16
// CTA 128m x 64n x 2 outputs, 8 warps.  BK=32, 4-stage, hoisted ldsm offsets.
// ===========================================================================
__global__ __launch_bounds__(256, 2)
void fused_gemm12_kernel(const __half* __restrict__ Af,
                         const __half* __restrict__ B1,
                         const __half* __restrict__ B3,
                         const int* __restrict__ langs,
                         __half* __restrict__ outH)
{
    extern __shared__ char smem[];
    const uint32_t sbase = smem_to_u32(smem);

    const int tid = threadIdx.x;
    const int wid = tid >> 5;
    const int lane = tid & 31;
    const int out_sel = wid >> 2;          // 0: W1(a), 1: W3(b)
    const int w4 = wid & 3;
    const int wm = w4 >> 1;
    const int wn = w4 & 1;

    const int bz = blockIdx.z;
    const int m0 = blockIdx.y * 128;
    const int n0 = blockIdx.x * 64;

    const int lang = langs[bz];
    int e = lang - 4; if (e < 0) e = 0; if (e > 7) e = 7;

    const long aRow0 = (long)bz * S_ + m0;
    const long wBase = (long)e * D_ * F_;
    const int NC = D_ / BK;    // 32

    // ---- hoisted global-load pointers + smem store offsets ----
    const int ar = tid >> 2;
    const int ac = tid & 3;
    const __half* pA = Af + (aRow0 + ar) * (long)D_ + ac * 8;
    const uint32_t sA0 = a_off(ar, ac);
    const uint32_t sA1 = a_off(ar + 64, ac);

    const int br = tid >> 3;
    const int bc8 = tid & 7;
    const __half* pB1 = B1 + wBase + (long)br * F_ + n0 + bc8 * 8;
    const __half* pB3 = B3 + wBase + (long)br * F_ + n0 + bc8 * 8;
    const uint32_t sB = A_ARR + fb_off(br, bc8);

    // ---- hoisted ldsm read offsets (loop-invariant) ----
    uint32_t offA[4][2];
#pragma unroll
    for (int mt = 0; mt < 4; mt++) {
        int row = wm * 64 + mt * 16 + (lane & 15);
#pragma unroll
        for (int ks = 0; ks < 2; ks++)
            offA[mt][ks] = a_off(row, ks * 2 + (lane >> 4));
    }
    uint32_t offB[2][2];
#pragma unroll
    for (int ks = 0; ks < 2; ks++) {
        int brow = ks * 16 + (lane & 15);
#pragma unroll
        for (int half = 0; half < 2; half++)
            offB[ks][half] = fb_off(brow, wn * 4 + half * 2 + (lane >> 4));
    }

    float acc[4][4][4];
#pragma unroll
    for (int i = 0; i < 4; i++)
#pragma unroll
        for (int j = 0; j < 4; j++)
#pragma unroll
            for (int q = 0; q < 4; q++) acc[i][j][q] = 0.0f;

    // prologue: stages 0..2
#pragma unroll
    for (int s = 0; s < 3; s++) {
        const uint32_t st = sbase + s * F_STAGE;
        CP_ASYNC16(st + sA0, pA);
        CP_ASYNC16(st + sA1, pA + (long)64 * D_);
        CP_ASYNC16(st + sB, pB1);
        CP_ASYNC16(st + sB + FB_ARR, pB3);
        CP_COMMIT();
        pA += BK; pB1 += (long)BK * F_; pB3 += (long)BK * F_;
    }

    const uint32_t stBoff = A_ARR + out_sel * FB_ARR;

    for (int c = 0; c < NC; ++c) {
        CP_WAIT2();
        __syncthreads();
        if (c + 3 < NC) {
            const uint32_t st = sbase + ((c + 3) & 3) * F_STAGE;
            CP_ASYNC16(st + sA0, pA);
            CP_ASYNC16(st + sA1, pA + (long)64 * D_);
            CP_ASYNC16(st + sB, pB1);
            CP_ASYNC16(st + sB + FB_ARR, pB3);
            pA += BK; pB1 += (long)BK * F_; pB3 += (long)BK * F_;
        }
        CP_COMMIT();

        const uint32_t st = sbase + (c & 3) * F_STAGE;
        const uint32_t stB = st + stBoff;
#pragma unroll
        for (int ks = 0; ks < 2; ks++) {
            uint32_t bf[4][2];
#pragma unroll
            for (int half = 0; half < 2; half++) {
                uint32_t r0, r1, r2, r3;
                ldsm_x4_t(r0, r1, r2, r3, stB + offB[ks][half]);
                bf[half * 2][0] = r0; bf[half * 2][1] = r1;
                bf[half * 2 + 1][0] = r2; bf[half * 2 + 1][1] = r3;
            }
#pragma unroll
            for (int mt = 0; mt < 4; mt++) {
                uint32_t af[4];
                ldsm_x4(af[0], af[1], af[2], af[3], st + offA[mt][ks]);
#pragma unroll
                for (int nt = 0; nt < 4; nt++)
                    mma_16816(acc[mt][nt], af, bf[nt]);
            }
        }
    }

    // --- epilogue: a-warps dump acc to smem; b-warps apply gelu(a)*b ---
    __syncthreads();
    float* ex = (float*)smem;
    if (out_sel == 0) {
#pragma unroll
        for (int mt = 0; mt < 4; mt++)
#pragma unroll
            for (int nt = 0; nt < 4; nt++)
#pragma unroll
                for (int q = 0; q < 4; q++) {
                    int i = (mt * 4 + nt) * 4 + q;
                    ex[w4 * 2048 + i * 32 + lane] = acc[mt][nt][q];
                }
    }
    __syncthreads();
    if (out_sel == 1) {
        const int qr = lane >> 2;
        const int qc = (lane & 3) * 2;
#pragma unroll
        for (int mt = 0; mt < 4; mt++) {
#pragma unroll
            for (int half = 0; half < 2; half++) {
                const int gm = m0 + wm * 64 + mt * 16 + qr + half * 8;
                const long rowBase = ((long)bz * S_ + gm) * (long)F_;
#pragma unroll
                for (int nt = 0; nt < 4; nt++) {
                    const int gn = n0 + wn * 32 + nt * 8 + qc;
                    const long idx = rowBase + gn;
                    float b0 = acc[mt][nt][half * 2 + 0];
                    float b1 = acc[mt][nt][half * 2 + 1];
                    int i0 = (mt * 4 + nt) * 4 + half * 2;
                    float a0 = ex[w4 * 2048 + i0 * 32 + lane];
                    float a1 = ex[w4 * 2048 + (i0 + 1) * 32 + lane];
                    float g0 = 0.5f * a0 * (1.0f + erff(a0 * 0.70710678118654752f));
                    float g1 = 0.5f * a1 * (1.0f + erff(a1 * 0.70710678118654752f));
                    union { uint32_t u; __half h[2]; } uh;
                    uh.h[0] = __float2half_rn(g0 * b0);
                    uh.h[1] = __float2half_rn(g1 * b1);
                    *(uint32_t*)(outH + idx) = uh.u;
                }
            }
        }
    }
}

// ===========================================================================
// GEMM3 (split-K=2): out += rw * (h[.., Khalf] @ W2[Khalf, ..]) via REDG
// CTA 128m x 128n, 8 warps 2m x 4n.  BK=32, 4-stage, hoisted ldsm offsets.
// ===========================================================================
__global__ __launch_bounds__(256, 2)
void gemm3_kernel(const __half* __restrict__ Af,
                  const __half* __restrict__ Bf,
                  const int* __restrict__ langs,
                  float* __restrict__ out)
{
    extern __shared__ char smem[];
    const uint32_t sbase = smem_to_u32(smem);

    const int tid = threadIdx.x;
    const int wid = tid >> 5;
    const int lane = tid & 31;
    const int wm = wid >> 2;
    const int wn = wid & 3;

    const int z = blockIdx.z;
    const int bz = z >> 1;
    const int kh = z & 1;
    const int m0 = blockIdx.y * 128;
    const int n0 = blockIdx.x * 128;

    const int lang = langs[bz];
    int e = lang - 4; if (e < 0) e = 0; if (e > 7) e = 7;
    const int cnt = (lang > 3) ? 1 : 0;
    const float rw = (cnt == 0) ? 1.0f : (1.0f / (float)cnt);

    const long aRow0 = (long)bz * S_ + m0;
    const long wBase = (long)e * F_ * D_;
    const int kBase = kh * (F_ / 2);
    const int NC = (F_ / 2) / BK;         // 64

    // ---- hoisted global-load pointers + smem store offsets ----
    const int ar = tid >> 2;
    const int ac = tid & 3;
    const __half* pA = Af + (aRow0 + ar) * (long)F_ + kBase + ac * 8;
    const uint32_t sA0 = a_off(ar, ac);
    const uint32_t sA1 = a_off(ar + 64, ac);

    const int br = tid >> 4;
    const int bc16 = tid & 15;
    const __half* pB = Bf + wBase + (long)(kBase + br) * D_ + n0 + bc16 * 8;
    const uint32_t sB0 = A_ARR + gb_off(br, bc16);
    const uint32_t sB1 = A_ARR + gb_off(br + 16, bc16);

    // ---- hoisted ldsm read offsets ----
    uint32_t offA[4][2];
#pragma unroll
    for (int mt = 0; mt < 4; mt++) {
        int row = wm * 64 + mt * 16 + (lane & 15);
#pragma unroll
        for (int ks = 0; ks < 2; ks++)
            offA[mt][ks] = a_off(row, ks * 2 + (lane >> 4));
    }
    uint32_t offB[2][2];
#pragma unroll
    for (int ks = 0; ks < 2; ks++) {
        int brow = ks * 16 + (lane & 15);
#pragma unroll
        for (int half = 0; half < 2; half++)
            offB[ks][half] = gb_off(brow, wn * 4 + half * 2 + (lane >> 4));
    }

    float acc[4][4][4];
#pragma unroll
    for (int i = 0; i < 4; i++)
#pragma unroll
        for (int j = 0; j < 4; j++)
#pragma unroll
            for (int q = 0; q < 4; q++) acc[i][j][q] = 0.0f;

#pragma unroll
    for (int s = 0; s < 3; s++) {
        const uint32_t st = sbase + s * G_STAGE;
        CP_ASYNC16(st + sA0, pA);
        CP_ASYNC16(st + sA1, pA + (long)64 * F_);
        CP_ASYNC16(st + sB0, pB);
        CP_ASYNC16(st + sB1, pB + (long)16 * D_);
        CP_COMMIT();
        pA += BK; pB += (long)BK * D_;
    }

    for (int c = 0; c < NC; ++c) {
        CP_WAIT2();
        __syncthreads();
        if (c + 3 < NC) {
            const uint32_t st = sbase + ((c + 3) & 3) * G_STAGE;
            CP_ASYNC16(st + sA0, pA);
            CP_ASYNC16(st + sA1, pA + (long)64 * F_);
            CP_ASYNC16(st + sB0, pB);
            CP_ASYNC16(st + sB1, pB + (long)16 * D_);
            pA += BK; pB += (long)BK * D_;
        }
        CP_COMMIT();

        const uint32_t st = sbase + (c & 3) * G_STAGE;
        const uint32_t stB = st + A_ARR;
#pragma unroll
        for (int ks = 0; ks < 2; ks++) {
            uint32_t bf[4][2];
#pragma unroll
            for (int half = 0; half < 2; half++) {
                uint32_t r0, r1, r2, r3;
                ldsm_x4_t(r0, r1, r2, r3, stB + offB[ks][half]);
                bf[half * 2][0] = r0; bf[half * 2][1] = r1;
                bf[half * 2 + 1][0] = r2; bf[half * 2 + 1][1] = r3;
            }
#pragma unroll
            for (int mt = 0; mt < 4; mt++) {
                uint32_t af[4];
                ldsm_x4(af[0], af[1], af[2], af[3], st + offA[mt][ks]);
#pragma unroll
                for (int nt = 0; nt < 4; nt++)
                    mma_16816(acc[mt][nt], af, bf[nt]);
            }
        }
    }

    // epilogue: REDG-accumulate rw-scaled partials into pre-zeroed out
    const int qr = lane >> 2;
    const int qc = (lane & 3) * 2;
#pragma unroll
    for (int mt = 0; mt < 4; mt++) {
#pragma unroll
        for (int half = 0; half < 2; half++) {
            const int gm = m0 + wm * 64 + mt * 16 + qr + half * 8;
            const long rowBase = ((long)bz * S_ + gm) * (long)D_;
#pragma unroll
            for (int nt = 0; nt < 4; nt++) {
                const int gn = n0 + wn * 32 + nt * 8 + qc;
                atomicAdd(out + rowBase + gn, acc[mt][nt][half * 2] * rw);
                atomicAdd(out + rowBase + gn + 1, acc[mt][nt][half * 2 + 1] * rw);
            }
        }
    }
}

// ---------------------------------------------------------------------------
// Launch
// ---------------------------------------------------------------------------
extern "C" void kernel_launch(void* const* d_in, const int* in_sizes, int n_in,
                              void* d_out, int out_size)
{
    const float* x     = (const float*)d_in[0];
    const float* w1    = (const float*)d_in[1];
    const float* w2    = (const float*)d_in[2];
    const float* w3    = (const float*)d_in[3];
    const int*   langs = (const int*)  d_in[4];
    float* out = (float*)d_out;

    __half *xf, *w1f, *w3f, *w2f, *hf;
    cudaGetSymbolAddress((void**)&xf,  g_xf);
    cudaGetSymbolAddress((void**)&w1f, g_w1f);
    cudaGetSymbolAddress((void**)&w3f, g_w3f);
    cudaGetSymbolAddress((void**)&w2f, g_w2f);
    cudaGetSymbolAddress((void**)&hf,  g_hf);

    cudaFuncSetAttribute(fused_gemm12_kernel,
                         cudaFuncAttributeMaxDynamicSharedMemorySize, F_SMEM);
    cudaFuncSetAttribute(gemm3_kernel,
                         cudaFuncAttributeMaxDynamicSharedMemorySize, G_SMEM);

    // 0) zero output (REDG accumulation target)
    {
        long n4 = (long)B_ * S_ * D_ / 4;
        zero_kernel<<<(unsigned)((n4 / 2) / 256), 256>>>((float4*)out, n4);
    }
    // 1) prep: fp16 conversions (weights expert-gated)
    {
        long nx = (long)B_ * S_ * D_ / 4;
        convert_x_kernel<<<(unsigned)((nx / 2) / 256), 256>>>(x, xf, nx);
        unsigned wb = (unsigned)((((long)D_ * F_ / 4) / 2) / 256);
        dim3 gw(wb, 3, E_);
        convert_w_kernel<<<gw, 256>>>(w1, w3, w2, w1f, w3f, w2f, langs);
    }
    // 2) fused GEMM1+GEMM2 + GLU -> h (fp16)
    {
        dim3 grid(F_ / 64, S_ / 128, B_);
        fused_gemm12_kernel<<<grid, 256, F_SMEM>>>(xf, w1f, w3f, langs, hf);
    }
    // 3) GEMM3 split-K=2, REDG into out
    {
        dim3 grid(D_ / 128, S_ / 128, B_ * 2);
        gemm3_kernel<<<grid, 256, G_SMEM>>>(hf, w2f, langs, out);
    }
}